// round 9
// baseline (speedup 1.0000x reference)
#include <cuda_runtime.h>
#include <math.h>

#define N_ATOMS 512
#define NQC     8
#define NT      32      // targets per block
#define NS      16      // sources per chunk
#define NCH     32      // source chunks
#define TPB     128     // NT * (NQC/2)
#define NTQ     (N_ATOMS * NQC)   // 4096
#define NTB     (N_ATOMS / NT)    // 16 target blocks

typedef unsigned long long ull;

// compact accumulators: [18][tq] (288 KB, L2-resident). Zero at process start;
// finalize re-zeroes after consuming, so every replay sees clean state.
__device__ float g_acc[18 * NTQ];

// ---- f32x2 packed helpers (Blackwell FFMA2 path; PTX-only) ----
__device__ __forceinline__ ull f2b(float v) {            // broadcast {v,v}
    ull r; asm("mov.b64 %0, {%1, %1};" : "=l"(r) : "f"(v)); return r;
}
__device__ __forceinline__ ull fma2(ull a, ull b, ull c) {
    ull d; asm("fma.rn.f32x2 %0, %1, %2, %3;" : "=l"(d) : "l"(a), "l"(b), "l"(c)); return d;
}
__device__ __forceinline__ ull mul2(ull a, ull b) {
    ull d; asm("mul.rn.f32x2 %0, %1, %2;" : "=l"(d) : "l"(a), "l"(b)); return d;
}
__device__ __forceinline__ ull add2(ull a, ull b) {
    ull d; asm("add.rn.f32x2 %0, %1, %2;" : "=l"(d) : "l"(a), "l"(b)); return d;
}
__device__ __forceinline__ void f2unpack(ull v, float& lo, float& hi) {
    asm("mov.b64 {%0, %1}, %2;" : "=f"(lo), "=f"(hi) : "l"(v));
}

__global__ __launch_bounds__(TPB, 4)
void pairs_kernel(const float* __restrict__ gq, const float* __restrict__ gr,
                  const float* __restrict__ gu, const float* __restrict__ gQ,
                  float* __restrict__ out)
{
    __shared__ __align__(16) float s_sr[NS * 3];
    __shared__ __align__(16) float s_tr[NT * 3];
    // channel data interleaved per channel-pair, stride 24 floats (96 B):
    // u64 slots: {q, ux, uy, uz, S00, S01, S02, S11, S12, S22, trq, pad}
    __shared__ __align__(16) float s_srcP[NS * 4 * 24];            // 6 KB
    // pair scalars pre-broadcast-packed, stride 10 u64 (80 B, conflict-free):
    // slots {g, c1, c2, c3, c4, dx, dy, dz, pad, pad}
    __shared__ __align__(16) ull s_pairP[NS * NT * 10];            // 40 KB

    const int tid = threadIdx.x;
    const int t0  = blockIdx.x * NT;
    const int s0  = blockIdx.y * NS;

    if (blockIdx.x == 0 && blockIdx.y == 0 && tid == 0)
        out[0] = 0.0f;   // pot accumulator, consumed by finalize

    // ---- phase 1: stage positions + interleaved channel data ----
    for (int i = tid; i < NS * 3; i += TPB) s_sr[i] = gr[s0 * 3 + i];
    for (int i = tid; i < NT * 3; i += TPB) s_tr[i] = gr[t0 * 3 + i];
    for (int i = tid; i < NS * NQC; i += TPB) {
        const int s = i >> 3, qc = i & 7;
        const int half = qc & 1;
        float* b = &s_srcP[((s * 4 + (qc >> 1)) * 24) + half];
        const float qv = gq[s0 * NQC + i];
        const float* up = gu + (s0 * NQC + i) * 3;
        const float* Qp = gQ + (s0 * NQC + i) * 9;
        const float q00 = Qp[0], q01 = Qp[1], q02 = Qp[2];
        const float q10 = Qp[3], q11 = Qp[4], q12 = Qp[5];
        const float q20 = Qp[6], q21 = Qp[7], q22 = Qp[8];
        b[0]  = qv;
        b[2]  = up[0]; b[4] = up[1]; b[6] = up[2];
        b[8]  = q00 + q00; b[10] = q01 + q10; b[12] = q02 + q20;
        b[14] = q11 + q11; b[16] = q12 + q21; b[18] = q22 + q22;
        b[20] = q00 + q11 + q22;
        b[22] = 0.f;
    }
    __syncthreads();

    // ---- phase 2: pair scalar kernels, written pre-broadcast-packed ----
    const float A_ERF = 0.70710678118654752f;                         // 1/sqrt(2)
    const float NCE = (float)(90.4756 / (2.0 * 3.14159265358979323846));
    const float NCG = (float)((90.4756 / (2.0 * 3.14159265358979323846))
                              * 0.79788456080286536);                 // nc * 2a/sqrt(pi)

#pragma unroll
    for (int p = tid; p < NS * NT; p += TPB) {
        const int s  = p >> 5;
        const int tl = p & 31;
        float dx = s_tr[tl * 3 + 0] - s_sr[s * 3 + 0];
        float dy = s_tr[tl * 3 + 1] - s_sr[s * 3 + 1];
        float dz = s_tr[tl * 3 + 2] - s_sr[s * 3 + 2];
        float g = 0.f, c1 = 0.f, c2 = 0.f, c3 = 0.f, c4 = 0.f;
        if (t0 + tl != s0 + s) {
            float r2 = dx * dx + dy * dy + dz * dz;
            float rr = sqrtf(r2);
            float E  = NCE * erff(A_ERF * rr);
            float G  = NCG * expf(-0.5f * rr * rr);
            float ir = 1.0f / rr;
            float ir2 = ir * ir,  ir3 = ir2 * ir,  ir4 = ir2 * ir2, ir5 = ir4 * ir;
            float ir6 = ir4 * ir2, ir7 = ir6 * ir, ir8 = ir4 * ir4, ir9 = ir8 * ir;
            g  = E * ir;
            c1 = G * ir2 - E * ir3;
            c2 = 3.0f * E * ir5 - 3.0f * G * ir4 - G * ir2;
            c3 = -15.0f * E * ir7 + 15.0f * G * ir6 + 5.0f * G * ir4 + G * ir2;
            c4 = 105.0f * E * ir9 - 105.0f * G * ir8 - 35.0f * G * ir6
                 - 7.0f * G * ir4 - G * ir2;
        }
        ull* wp = &s_pairP[(size_t)p * 10];
        wp[0] = f2b(g);  wp[1] = f2b(c1); wp[2] = f2b(c2); wp[3] = f2b(c3);
        wp[4] = f2b(c4); wp[5] = f2b(dx); wp[6] = f2b(dy); wp[7] = f2b(dz);
    }
    __syncthreads();

    // ---- phase 3: packed f32x2 accumulation (2 channels per thread) ----
    const int tl = tid >> 2;
    const int cp = tid & 3;           // channel pair: channels 2cp, 2cp+1
    const ull HALFP = f2b(0.5f);

    ull A0 = 0, A1 = 0, A2 = 0;
    ull Eux = 0, Euy = 0, Euz = 0;
    ull EQx = 0, EQy = 0, EQz = 0;    // stores  Σ(cD*d + c2*s); finalize *-0.5
    ull Efx = 0, Efy = 0, Efz = 0;    // stores  Σ(c1*q*d);      finalize * -1
    ull Qxx = 0, Qxy = 0, Qxz = 0, Qyy = 0, Qyz = 0, Qzz = 0;

#pragma unroll 4
    for (int s = 0; s < NS; s++) {
        const ulonglong2* pp = (const ulonglong2*)&s_pairP[(size_t)(s * NT + tl) * 10];
        const ulonglong2 P0 = pp[0], P1 = pp[1], P2 = pp[2], P3 = pp[3];
        const ull gP = P0.x, c1P = P0.y, c2P = P1.x, c3P = P1.y;
        const ull c4P = P2.x, dxP = P2.y, dyP = P3.x, dzP = P3.y;

        const ulonglong2* sp = (const ulonglong2*)&s_srcP[(s * 4 + cp) * 24];
        const ulonglong2 V0 = sp[0], V1 = sp[1], V2 = sp[2];
        const ulonglong2 V3 = sp[3], V4 = sp[4], V5 = sp[5];
        const ull q2 = V0.x, ux2 = V0.y, uy2 = V1.x, uz2 = V1.y;
        const ull S00 = V2.x, S01 = V2.y, S02 = V3.x, S11 = V3.y;
        const ull S12 = V4.x, S22 = V4.y, trq2 = V5.x;

        const ull ud = fma2(ux2, dxP, fma2(uy2, dyP, mul2(uz2, dzP)));
        const ull sx = fma2(S00, dxP, fma2(S01, dyP, mul2(S02, dzP)));
        const ull sy = fma2(S01, dxP, fma2(S11, dyP, mul2(S12, dzP)));
        const ull sz = fma2(S02, dxP, fma2(S12, dyP, mul2(S22, dzP)));
        const ull dQd = mul2(HALFP, fma2(dxP, sx, fma2(dyP, sy, mul2(dzP, sz))));

        A0 = fma2(gP, q2, A0);
        A1 = fma2(c1P, ud, A1);                       // -1 at finalize
        A2 = fma2(c2P, dQd, A2);                      // 0.5 at finalize
        A2 = fma2(c1P, trq2, A2);

        const ull t2u = mul2(c2P, ud);
        Eux = fma2(t2u, dxP, fma2(c1P, ux2, Eux));
        Euy = fma2(t2u, dyP, fma2(c1P, uy2, Euy));
        Euz = fma2(t2u, dzP, fma2(c1P, uz2, Euz));

        const ull cD = fma2(c3P, dQd, mul2(c2P, trq2));
        EQx = fma2(cD, dxP, fma2(c2P, sx, EQx));      // -0.5 at finalize
        EQy = fma2(cD, dyP, fma2(c2P, sy, EQy));
        EQz = fma2(cD, dzP, fma2(c2P, sz, EQz));

        const ull t1q = mul2(c1P, q2);
        Efx = fma2(t1q, dxP, Efx);                    // -1 at finalize
        Efy = fma2(t1q, dyP, Efy);
        Efz = fma2(t1q, dzP, Efz);

        const ull cA = fma2(c4P, dQd, mul2(c3P, trq2));
        const ull hx = mul2(c3P, sx), hy = mul2(c3P, sy), hz = mul2(c3P, sz);

        Qxx = fma2(cA, mul2(dxP, dxP), Qxx);
        Qxx = fma2(add2(hx, hx), dxP, Qxx);
        Qxx = fma2(c2P, S00, add2(Qxx, cD));
        Qyy = fma2(cA, mul2(dyP, dyP), Qyy);
        Qyy = fma2(add2(hy, hy), dyP, Qyy);
        Qyy = fma2(c2P, S11, add2(Qyy, cD));
        Qzz = fma2(cA, mul2(dzP, dzP), Qzz);
        Qzz = fma2(add2(hz, hz), dzP, Qzz);
        Qzz = fma2(c2P, S22, add2(Qzz, cD));
        Qxy = fma2(cA, mul2(dxP, dyP), Qxy);
        Qxy = fma2(hx, dyP, Qxy);
        Qxy = fma2(hy, dxP, Qxy);
        Qxy = fma2(c2P, S01, Qxy);
        Qxz = fma2(cA, mul2(dxP, dzP), Qxz);
        Qxz = fma2(hx, dzP, Qxz);
        Qxz = fma2(hz, dxP, Qxz);
        Qxz = fma2(c2P, S02, Qxz);
        Qyz = fma2(cA, mul2(dyP, dzP), Qyz);
        Qyz = fma2(hy, dzP, Qyz);
        Qyz = fma2(hz, dyP, Qyz);
        Qyz = fma2(c2P, S12, Qyz);
    }

    // ---- accumulate into compact L2-resident array (2 channels/thread) ----
    const int tqb = (t0 + tl) * NQC + 2 * cp;
    const ull acc[18] = {A0, A1, A2, Eux, Euy, Euz, EQx, EQy, EQz,
                         Efx, Efy, Efz, Qxx, Qxy, Qxz, Qyy, Qyz, Qzz};
#pragma unroll
    for (int k = 0; k < 18; k++) {
        float lo, hi; f2unpack(acc[k], lo, hi);
        atomicAdd(&g_acc[k * NTQ + tqb],     lo);
        atomicAdd(&g_acc[k * NTQ + tqb + 1], hi);
    }
}

// PDL secondary: starts while pairs drains, prefetches inputs that pairs does
// not write, then grid-syncs before touching g_acc / out.
__global__ __launch_bounds__(32)
void finalize_kernel(const float* __restrict__ gq, const float* __restrict__ gu,
                     const float* __restrict__ gQ, const float* __restrict__ gkap,
                     const float* __restrict__ gal, float* __restrict__ out)
{
    const int tqi = blockIdx.x * 32 + threadIdx.x;

    // prefetch inputs independent of pairs' outputs
    const float qv  = gq[tqi];
    const float kap = gkap[tqi];
    const float al  = gal[tqi];
    const float ux = gu[tqi * 3 + 0], uy = gu[tqi * 3 + 1], uz = gu[tqi * 3 + 2];
    float Qpv[9];
#pragma unroll
    for (int k = 0; k < 9; k++) Qpv[k] = gQ[tqi * 9 + k];

    // wait for pairs_kernel completion
    cudaGridDependencySynchronize();

    float acc[18];
#pragma unroll
    for (int k = 0; k < 18; k++)
        acc[k] = g_acc[k * NTQ + tqi];
#pragma unroll
    for (int k = 0; k < 18; k++)
        g_acc[k * NTQ + tqi] = 0.0f;          // self-clean for next replay

    const float A0 = acc[0];
    const float A1 = -acc[1];                 // sign folded out of pairs
    const float A2 = 0.5f * acc[2];           // 0.5 folded out of pairs
    const float Eux = acc[3], Euy = acc[4], Euz = acc[5];
    const float EQx = -0.5f * acc[6], EQy = -0.5f * acc[7], EQz = -0.5f * acc[8];
    const float Efx = -acc[9], Efy = -acc[10], Efz = -acc[11];
    const float Qxx = acc[12], Qxy = acc[13], Qxz = acc[14];
    const float Qyy = acc[15], Qyz = acc[16], Qzz = acc[17];

    const float ephi = A0 + A1 + A2;
    out[1 + tqi] = -kap * ephi;                               // q_induced

    const float ex = Efx + Eux + EQx;
    const float ey = Efy + Euy + EQy;
    const float ez = Efz + Euz + EQz;
    out[1 + NTQ + tqi * 3 + 0] = al * ex;                     // u_induced
    out[1 + NTQ + tqi * 3 + 1] = al * ey;
    out[1 + NTQ + tqi * 3 + 2] = al * ez;

    const float qQQ = Qpv[0] * Qxx + Qpv[4] * Qyy + Qpv[8] * Qzz
                    + (Qpv[1] + Qpv[3]) * Qxy + (Qpv[2] + Qpv[6]) * Qxz
                    + (Qpv[5] + Qpv[7]) * Qyz;
    const float uEu = ux * Eux + uy * Euy + uz * Euz;
    const float uEQ = ux * EQx + uy * EQy + uz * EQz;
    const float e2  = ex * ex + ey * ey + ez * ez;

    float pot = 0.5f * A0 * qv + A1 * qv - 0.5f * uEu + qv * A2
              + 0.125f * qQQ - uEQ
              - 0.5f * kap * ephi * ephi
              - 0.5f * al * e2;

#pragma unroll
    for (int off = 16; off > 0; off >>= 1)
        pot += __shfl_xor_sync(0xFFFFFFFFu, pot, off);
    if (threadIdx.x == 0) atomicAdd(&out[0], pot);
}

extern "C" void kernel_launch(void* const* d_in, const int* in_sizes, int n_in,
                              void* d_out, int out_size)
{
    (void)in_sizes; (void)n_in; (void)out_size;
    const float* q     = (const float*)d_in[0];
    const float* r     = (const float*)d_in[1];
    // d_in[2] = cell (zero -> realspace branch), d_in[3] = batch: unused
    const float* u     = (const float*)d_in[4];
    const float* quad  = (const float*)d_in[5];
    const float* kappa = (const float*)d_in[6];
    const float* alpha = (const float*)d_in[7];
    float* out = (float*)d_out;

    pairs_kernel<<<dim3(NTB, NCH), TPB>>>(q, r, u, quad, out);

    cudaLaunchConfig_t cfg = {};
    cfg.gridDim  = dim3(NTQ / 32, 1, 1);
    cfg.blockDim = dim3(32, 1, 1);
    cfg.dynamicSmemBytes = 0;
    cfg.stream = 0;
    cudaLaunchAttribute attrs[1];
    attrs[0].id = cudaLaunchAttributeProgrammaticStreamSerialization;
    attrs[0].val.programmaticStreamSerializationAllowed = 1;
    cfg.attrs = attrs;
    cfg.numAttrs = 1;
    cudaLaunchKernelEx(&cfg, finalize_kernel, q, u, quad, kappa, alpha, out);
}

// round 10
// speedup vs baseline: 1.0941x; 1.0941x over previous
#include <cuda_runtime.h>
#include <math.h>

#define N_ATOMS 512
#define NQC     8
#define NT      16      // targets per block
#define NS      16      // sources per chunk
#define NCH     32      // source chunks
#define TPB     128     // NT * NQC
#define NTQ     (N_ATOMS * NQC)   // 4096
#define NTB     (N_ATOMS / NT)    // 32 target blocks

// compact accumulators, grouped for vector RED atomics (288 KB, L2-resident):
//   g_acc4[g][tqi] holds acc[4g .. 4g+3]   (g = 0..3)
//   g_acc2[tqi]    holds acc[16..17]
// Zero at process start; finalize re-zeroes after consuming.
__device__ __align__(16) float4 g_acc4[4 * NTQ];
__device__ __align__(8)  float2 g_acc2[NTQ];

__device__ __forceinline__ void red_add_v4(float4* p, float a, float b, float c, float d) {
    asm volatile("red.global.add.v4.f32 [%0], {%1, %2, %3, %4};"
                 :: "l"(p), "f"(a), "f"(b), "f"(c), "f"(d) : "memory");
}
__device__ __forceinline__ void red_add_v2(float2* p, float a, float b) {
    asm volatile("red.global.add.v2.f32 [%0], {%1, %2};"
                 :: "l"(p), "f"(a), "f"(b) : "memory");
}

__global__ __launch_bounds__(TPB, 8)
void pairs_kernel(const float* __restrict__ gq, const float* __restrict__ gr,
                  const float* __restrict__ gu, const float* __restrict__ gQ,
                  float* __restrict__ out)
{
    __shared__ __align__(16) float s_sr[NS * 3];
    __shared__ __align__(16) float s_tr[NT * 3];
    // packed source-channel data, stride 12: {q,ux,uy,uz | S00,S01,S02,S11 | S12,S22,trq,0}
    __shared__ __align__(16) float s_src[NS * NQC * 12];    // 6 KB
    __shared__ __align__(16) float s_pair[NS * NT * 8];     // 8 KB {g,c1,c2,c3,c4,dx,dy,dz}

    const int tid = threadIdx.x;
    const int t0  = blockIdx.x * NT;
    const int s0  = blockIdx.y * NS;

    if (blockIdx.x == 0 && blockIdx.y == 0 && tid == 0)
        out[0] = 0.0f;   // pot accumulator, consumed by finalize after this grid completes

    // ---- phase 1: stage source + target data into smem ----
    for (int i = tid; i < NS * 3; i += TPB) s_sr[i] = gr[s0 * 3 + i];
    for (int i = tid; i < NT * 3; i += TPB) s_tr[i] = gr[t0 * 3 + i];
    for (int i = tid; i < NS * NQC; i += TPB) {
        const float qv = gq[s0 * NQC + i];
        const float* up = gu + (s0 * NQC + i) * 3;
        const float* Qp = gQ + (s0 * NQC + i) * 9;
        const float q00 = Qp[0], q01 = Qp[1], q02 = Qp[2];
        const float q10 = Qp[3], q11 = Qp[4], q12 = Qp[5];
        const float q20 = Qp[6], q21 = Qp[7], q22 = Qp[8];
        float4* d = (float4*)&s_src[i * 12];
        d[0] = make_float4(qv, up[0], up[1], up[2]);
        d[1] = make_float4(q00 + q00, q01 + q10, q02 + q20, q11 + q11);
        d[2] = make_float4(q12 + q21, q22 + q22, q00 + q11 + q22, 0.f);
    }
    __syncthreads();

    // ---- phase 2: pair scalar kernels (g, D1..D4)*nc and displacement ----
    const float A_ERF = 0.70710678118654752f;                         // 1/sqrt(2)
    const float NCE = (float)(90.4756 / (2.0 * 3.14159265358979323846));
    const float NCG = (float)((90.4756 / (2.0 * 3.14159265358979323846))
                              * 0.79788456080286536);                 // nc * 2a/sqrt(pi)

#pragma unroll
    for (int p = tid; p < NS * NT; p += TPB) {
        const int s  = p >> 4;
        const int tl = p & 15;
        float dx = s_tr[tl * 3 + 0] - s_sr[s * 3 + 0];
        float dy = s_tr[tl * 3 + 1] - s_sr[s * 3 + 1];
        float dz = s_tr[tl * 3 + 2] - s_sr[s * 3 + 2];
        float g = 0.f, c1 = 0.f, c2 = 0.f, c3 = 0.f, c4 = 0.f;
        if (t0 + tl != s0 + s) {
            float r2 = dx * dx + dy * dy + dz * dz;
            float rr = sqrtf(r2);
            float E  = NCE * erff(A_ERF * rr);
            float G  = NCG * expf(-0.5f * rr * rr);
            float ir = 1.0f / rr;
            float ir2 = ir * ir,  ir3 = ir2 * ir,  ir4 = ir2 * ir2, ir5 = ir4 * ir;
            float ir6 = ir4 * ir2, ir7 = ir6 * ir, ir8 = ir4 * ir4, ir9 = ir8 * ir;
            g  = E * ir;
            c1 = G * ir2 - E * ir3;
            c2 = 3.0f * E * ir5 - 3.0f * G * ir4 - G * ir2;                       // 2*a2 = 1
            c3 = -15.0f * E * ir7 + 15.0f * G * ir6 + 5.0f * G * ir4 + G * ir2;   // 10*a2=5, 4*a2^2=1
            c4 = 105.0f * E * ir9 - 105.0f * G * ir8 - 35.0f * G * ir6
                 - 7.0f * G * ir4 - G * ir2;                                      // 70a2=35, 28a2^2=7, 8a2^3=1
        }
        float4* op = (float4*)&s_pair[p * 8];
        op[0] = make_float4(g, c1, c2, c3);
        op[1] = make_float4(c4, dx, dy, dz);
    }
    __syncthreads();

    // ---- phase 3: per-(target, channel) accumulation over the source tile ----
    const int tl = tid >> 3;
    const int qc = tid & 7;

    float A0 = 0.f, A1 = 0.f, A2 = 0.f;
    float Eux = 0.f, Euy = 0.f, Euz = 0.f;
    float EQx = 0.f, EQy = 0.f, EQz = 0.f;
    float Efx = 0.f, Efy = 0.f, Efz = 0.f;
    float Qxx = 0.f, Qxy = 0.f, Qxz = 0.f, Qyy = 0.f, Qyz = 0.f, Qzz = 0.f;

#pragma unroll 8
    for (int s = 0; s < NS; s++) {
        const float4 pa = *(const float4*)&s_pair[(s * NT + tl) * 8];
        const float4 pb = *(const float4*)&s_pair[(s * NT + tl) * 8 + 4];
        const float g  = pa.x, c1 = pa.y, c2 = pa.z, c3 = pa.w;
        const float c4 = pb.x, dx = pb.y, dy = pb.z, dz = pb.w;
        const float4 f0 = *(const float4*)&s_src[(s * NQC + qc) * 12];
        const float4 f1 = *(const float4*)&s_src[(s * NQC + qc) * 12 + 4];
        const float4 f2 = *(const float4*)&s_src[(s * NQC + qc) * 12 + 8];
        const float qs = f0.x, ux = f0.y, uy = f0.z, uz = f0.w;
        const float S00 = f1.x, S01 = f1.y, S02 = f1.z, S11 = f1.w;
        const float S12 = f2.x, S22 = f2.y, trq = f2.z;

        const float ud  = fmaf(ux, dx, fmaf(uy, dy, uz * dz));
        // s = S·d  (== Q·d + Qᵀ·d);  dQd = ½ dᵀS d
        const float sx = fmaf(S00, dx, fmaf(S01, dy, S02 * dz));
        const float sy = fmaf(S01, dx, fmaf(S11, dy, S12 * dz));
        const float sz = fmaf(S02, dx, fmaf(S12, dy, S22 * dz));
        const float dQd = 0.5f * fmaf(dx, sx, fmaf(dy, sy, dz * sz));

        // potentials at target
        A0 = fmaf(g, qs, A0);
        A1 = fmaf(-c1, ud, A1);
        A2 = fmaf(0.5f * c2, dQd, A2);
        A2 = fmaf(0.5f * c1, trq, A2);

        // E_u (dipole field)
        const float t2u = c2 * ud;
        Eux = fmaf(t2u, dx, fmaf(c1, ux, Eux));
        Euy = fmaf(t2u, dy, fmaf(c1, uy, Euy));
        Euz = fmaf(t2u, dz, fmaf(c1, uz, Euz));

        // shared: cD = c3*dQd + c2*trq  (also = -2*Aq)
        const float cD = fmaf(c3, dQd, c2 * trq);

        // E_Q (quadrupole field):  Aq = -0.5*cD, Bq = -0.5*c2
        const float Aq = -0.5f * cD;
        const float Bq = -0.5f * c2;
        EQx = fmaf(Aq, dx, fmaf(Bq, sx, EQx));
        EQy = fmaf(Aq, dy, fmaf(Bq, sy, EQy));
        EQz = fmaf(Aq, dz, fmaf(Bq, sz, EQz));

        // field from charges
        const float t1q = c1 * qs;
        Efx = fmaf(-t1q, dx, Efx);
        Efy = fmaf(-t1q, dy, Efy);
        Efz = fmaf(-t1q, dz, Efz);

        // QQ (symmetric 3x3)
        const float cA = fmaf(c4, dQd, c3 * trq);
        const float hx = c3 * sx, hy = c3 * sy, hz = c3 * sz;
        Qxx = fmaf(cA, dx * dx, Qxx);
        Qxx = fmaf(hx + hx, dx, Qxx);
        Qxx = fmaf(c2, S00, Qxx + cD);
        Qyy = fmaf(cA, dy * dy, Qyy);
        Qyy = fmaf(hy + hy, dy, Qyy);
        Qyy = fmaf(c2, S11, Qyy + cD);
        Qzz = fmaf(cA, dz * dz, Qzz);
        Qzz = fmaf(hz + hz, dz, Qzz);
        Qzz = fmaf(c2, S22, Qzz + cD);
        Qxy = fmaf(cA, dx * dy, Qxy);
        Qxy = fmaf(hx, dy, Qxy);
        Qxy = fmaf(hy, dx, Qxy);
        Qxy = fmaf(c2, S01, Qxy);
        Qxz = fmaf(cA, dx * dz, Qxz);
        Qxz = fmaf(hx, dz, Qxz);
        Qxz = fmaf(hz, dx, Qxz);
        Qxz = fmaf(c2, S02, Qxz);
        Qyz = fmaf(cA, dy * dz, Qyz);
        Qyz = fmaf(hy, dz, Qyz);
        Qyz = fmaf(hz, dy, Qyz);
        Qyz = fmaf(c2, S12, Qyz);
    }

    // ---- accumulate partials with VECTOR reduction atomics (5 RED ops) ----
    const int tqi = (t0 + tl) * NQC + qc;
    red_add_v4(&g_acc4[0 * NTQ + tqi], A0,  A1,  A2,  Eux);
    red_add_v4(&g_acc4[1 * NTQ + tqi], Euy, Euz, EQx, EQy);
    red_add_v4(&g_acc4[2 * NTQ + tqi], EQz, Efx, Efy, Efz);
    red_add_v4(&g_acc4[3 * NTQ + tqi], Qxx, Qxy, Qxz, Qyy);
    red_add_v2(&g_acc2[tqi],           Qyz, Qzz);
}

// PDL secondary: starts while pairs drains, prefetches inputs that pairs does
// not write, then grid-syncs before touching the accumulators / out.
__global__ __launch_bounds__(32)
void finalize_kernel(const float* __restrict__ gq, const float* __restrict__ gu,
                     const float* __restrict__ gQ, const float* __restrict__ gkap,
                     const float* __restrict__ gal, float* __restrict__ out)
{
    const int tqi = blockIdx.x * 32 + threadIdx.x;

    // prefetch inputs independent of pairs' outputs
    const float qv  = gq[tqi];
    const float kap = gkap[tqi];
    const float al  = gal[tqi];
    const float ux = gu[tqi * 3 + 0], uy = gu[tqi * 3 + 1], uz = gu[tqi * 3 + 2];
    float Qpv[9];
#pragma unroll
    for (int k = 0; k < 9; k++) Qpv[k] = gQ[tqi * 9 + k];

    // wait for pairs_kernel completion (all its atomics + out[0]=0 visible)
    cudaGridDependencySynchronize();

    const float4 v0 = g_acc4[0 * NTQ + tqi];
    const float4 v1 = g_acc4[1 * NTQ + tqi];
    const float4 v2 = g_acc4[2 * NTQ + tqi];
    const float4 v3 = g_acc4[3 * NTQ + tqi];
    const float2 v4 = g_acc2[tqi];
    // re-zero for the next invocation (self-cleaning accumulators)
    const float4 z4 = make_float4(0.f, 0.f, 0.f, 0.f);
    g_acc4[0 * NTQ + tqi] = z4;
    g_acc4[1 * NTQ + tqi] = z4;
    g_acc4[2 * NTQ + tqi] = z4;
    g_acc4[3 * NTQ + tqi] = z4;
    g_acc2[tqi] = make_float2(0.f, 0.f);

    const float A0 = v0.x, A1 = v0.y, A2 = v0.z;
    const float Eux = v0.w, Euy = v1.x, Euz = v1.y;
    const float EQx = v1.z, EQy = v1.w, EQz = v2.x;
    const float Efx = v2.y, Efy = v2.z, Efz = v2.w;
    const float Qxx = v3.x, Qxy = v3.y, Qxz = v3.z;
    const float Qyy = v3.w, Qyz = v4.x, Qzz = v4.y;

    const float ephi = A0 + A1 + A2;
    out[1 + tqi] = -kap * ephi;                               // q_induced

    const float ex = Efx + Eux + EQx;
    const float ey = Efy + Euy + EQy;
    const float ez = Efz + Euz + EQz;
    out[1 + NTQ + tqi * 3 + 0] = al * ex;                     // u_induced
    out[1 + NTQ + tqi * 3 + 1] = al * ey;
    out[1 + NTQ + tqi * 3 + 2] = al * ez;

    const float qQQ = Qpv[0] * Qxx + Qpv[4] * Qyy + Qpv[8] * Qzz
                    + (Qpv[1] + Qpv[3]) * Qxy + (Qpv[2] + Qpv[6]) * Qxz
                    + (Qpv[5] + Qpv[7]) * Qyz;
    const float uEu = ux * Eux + uy * Euy + uz * Euz;
    const float uEQ = ux * EQx + uy * EQy + uz * EQz;
    const float e2  = ex * ex + ey * ey + ez * ez;

    float pot = 0.5f * A0 * qv + A1 * qv - 0.5f * uEu + qv * A2
              + 0.125f * qQQ - uEQ
              - 0.5f * kap * ephi * ephi
              - 0.5f * al * e2;

    // warp-shuffle reduction, one atomic per block
#pragma unroll
    for (int off = 16; off > 0; off >>= 1)
        pot += __shfl_xor_sync(0xFFFFFFFFu, pot, off);
    if (threadIdx.x == 0) atomicAdd(&out[0], pot);
}

extern "C" void kernel_launch(void* const* d_in, const int* in_sizes, int n_in,
                              void* d_out, int out_size)
{
    (void)in_sizes; (void)n_in; (void)out_size;
    const float* q     = (const float*)d_in[0];
    const float* r     = (const float*)d_in[1];
    // d_in[2] = cell (zero -> realspace branch), d_in[3] = batch: unused
    const float* u     = (const float*)d_in[4];
    const float* quad  = (const float*)d_in[5];
    const float* kappa = (const float*)d_in[6];
    const float* alpha = (const float*)d_in[7];
    float* out = (float*)d_out;

    pairs_kernel<<<dim3(NTB, NCH), TPB>>>(q, r, u, quad, out);

    // finalize with Programmatic Dependent Launch: overlaps launch + input
    // prefetch with pairs' tail; cudaGridDependencySynchronize() inside the
    // kernel provides the ordering on the accumulators / out.
    cudaLaunchConfig_t cfg = {};
    cfg.gridDim  = dim3(NTQ / 32, 1, 1);
    cfg.blockDim = dim3(32, 1, 1);
    cfg.dynamicSmemBytes = 0;
    cfg.stream = 0;
    cudaLaunchAttribute attrs[1];
    attrs[0].id = cudaLaunchAttributeProgrammaticStreamSerialization;
    attrs[0].val.programmaticStreamSerializationAllowed = 1;
    cfg.attrs = attrs;
    cfg.numAttrs = 1;
    cudaLaunchKernelEx(&cfg, finalize_kernel, q, u, quad, kappa, alpha, out);
}